// round 2
// baseline (speedup 1.0000x reference)
#include <cuda_runtime.h>
#include <cstdint>

// ============================================================================
// SampleNearestNeighborsLayer — exact JAX-semantics replay.
// Per batch b: 4096 sequential steps:
//   minU = min(used); cnt = #(used==minU); r = jax.random.randint(key_q,(),0,cnt)
//   center = r-th least-used point (index order); d_i = ||xyz_i - xyz_c||^2
//   ids = 16 smallest (d, i) lexicographic (== stable top_k(-d,16))
//   used[ids] += 1; used[center] += 100
// Output (float32): idx (8*4096*16) then pts (8*4096*3).
// ============================================================================

#define NQ      4096
#define NPTS    16384
#define KNN     16
#define BATCH   8
#define THREADS 1024
#define SMEM_BYTES 232448  // 192K xyz SoA + 32K used(u16) + 3K scratch = 227KB

__device__ uint32_t g_hb[BATCH * NQ];
__device__ uint32_t g_lb[BATCH * NQ];
__device__ uint32_t g_center[BATCH];

__device__ __forceinline__ uint32_t rotl32(uint32_t x, int r) {
    return (x << r) | (x >> (32 - r));
}

// Threefry-2x32, 20 rounds (JAX schedule).
__device__ __forceinline__ void tf2x32(uint32_t k0, uint32_t k1,
                                       uint32_t x0, uint32_t x1,
                                       uint32_t& o0, uint32_t& o1) {
    uint32_t ks2 = k0 ^ k1 ^ 0x1BD11BDAu;
    x0 += k0; x1 += k1;
#define TFR(r) { x0 += x1; x1 = rotl32(x1, (r)); x1 ^= x0; }
    TFR(13) TFR(15) TFR(26) TFR(6)
    x0 += k1;  x1 += ks2 + 1u;
    TFR(17) TFR(29) TFR(16) TFR(24)
    x0 += ks2; x1 += k0 + 2u;
    TFR(13) TFR(15) TFR(26) TFR(6)
    x0 += k0;  x1 += k1 + 3u;
    TFR(17) TFR(29) TFR(16) TFR(24)
    x0 += k1;  x1 += ks2 + 4u;
    TFR(13) TFR(15) TFR(26) TFR(6)
    x0 += ks2; x1 += k0 + 5u;
#undef TFR
    o0 = x0; o1 = x1;
}

// used[] stored as u16 pairs in u32 words; word W lives at usw(W).
// Makes the per-thread contiguous 8-word scan (W = 8t+k) conflict-free.
__device__ __forceinline__ uint32_t usw(uint32_t W) { return W ^ ((W >> 5) & 31u); }

extern "C" __global__ void __launch_bounds__(THREADS, 1)
snn_kernel(const float* __restrict__ xyz, float* __restrict__ out) {
    extern __shared__ unsigned char smem[];
    float*    sx     = (float*)smem;                        // 64 KB
    float*    sy     = sx + NPTS;                           // 64 KB
    float*    sz     = sy + NPTS;                           // 64 KB
    unsigned int* used32 = (unsigned int*)(sz + NPTS);      // 32 KB
    unsigned char* scr = (unsigned char*)(used32 + NPTS/2); // 3072 B, phase-unioned
    uint32_t* wred = (uint32_t*)scr;           // [32]  phase A (aliases wtD[0:32])
    uint32_t* wcnt = (uint32_t*)(scr + 128);   // [32]  phase A (aliases wtD[32:64])
    uint32_t* wtD  = (uint32_t*)scr;           // [512] phase B: per-warp top16 dist bits
    uint16_t* wtI  = (uint16_t*)(scr + 2048);  // [512] phase B: per-warp top16 indices

    const int tid  = threadIdx.x;
    const int b    = blockIdx.x;
    const int lane = tid & 31;
    const int wid  = tid >> 5;

    // ---- init: stage xyz (SoA), zero used, precompute randint bit-draws ----
    const float* g = xyz + (size_t)b * NPTS * 3;
    for (int i = tid; i < NPTS; i += THREADS) {
        sx[i] = g[3*i + 0];
        sy[i] = g[3*i + 1];
        sz[i] = g[3*i + 2];
    }
    for (int i = tid; i < NPTS/2; i += THREADS) used32[i] = 0u;

    {
        uint32_t bk0, bk1;
        tf2x32(0u, 42u, 0u, (uint32_t)b, bk0, bk1);          // batch key
        for (int q = tid; q < NQ; q += THREADS) {
            uint32_t qk0, qk1, a0, a1, e0, e1, x, y;
            tf2x32(bk0, bk1, 0u, (uint32_t)q, qk0, qk1);     // per-step key
            tf2x32(qk0, qk1, 0u, 0u, a0, a1);                // split[0]
            tf2x32(qk0, qk1, 0u, 1u, e0, e1);                // split[1]
            tf2x32(a0, a1, 0u, 0u, x, y);  g_hb[b*NQ + q] = x ^ y;
            tf2x32(e0, e1, 0u, 0u, x, y);  g_lb[b*NQ + q] = x ^ y;
        }
    }
    __syncthreads();

    const size_t OUT_PTS = (size_t)BATCH * NQ * KNN;

    for (int q = 0; q < NQ; ++q) {
        const int gq = b * NQ + q;
        const uint32_t hb = g_hb[gq];
        const uint32_t lb = g_lb[gq];

        // ============ Phase A: minU, cnt, rank-select center ============
        uint32_t pw[8];
        #pragma unroll
        for (int k = 0; k < 8; ++k)
            pw[k] = used32[usw((uint32_t)tid * 8u + (uint32_t)k)];

        uint32_t pm = pw[0];
        #pragma unroll
        for (int k = 1; k < 8; ++k) pm = __vminu2(pm, pw[k]);
        uint32_t lmin = min(pm & 0xFFFFu, pm >> 16);
        #pragma unroll
        for (int o = 16; o; o >>= 1)
            lmin = min(lmin, __shfl_xor_sync(0xFFFFFFFFu, lmin, o));
        if (lane == 0) wred[wid] = lmin;
        __syncthreads();                                    // bar1

        uint32_t minU = wred[0];
        #pragma unroll
        for (int w = 1; w < 32; ++w) minU = min(minU, wred[w]);

        uint32_t ci = 0;
        #pragma unroll
        for (int k = 0; k < 8; ++k)
            ci += (uint32_t)((pw[k] & 0xFFFFu) == minU) + (uint32_t)((pw[k] >> 16) == minU);
        uint32_t incl = ci;
        #pragma unroll
        for (int o = 1; o < 32; o <<= 1) {
            uint32_t v = __shfl_up_sync(0xFFFFFFFFu, incl, o);
            if (lane >= o) incl += v;
        }
        if (lane == 31) wcnt[wid] = incl;
        __syncthreads();                                    // bar2

        uint32_t cnt = 0, wexcl = 0;
        #pragma unroll
        for (int w = 0; w < 32; ++w) {
            uint32_t v = wcnt[w];
            if (w < wid) wexcl += v;
            cnt += v;
        }

        // jax.random.randint(key_q, (), 0, cnt) — all ops uint32, no overflow
        uint32_t span = cnt;
        uint32_t mlt  = 65536u % span;
        mlt = (mlt * mlt) % span;
        uint32_t rr = ((hb % span) * mlt + (lb % span)) % span;

        uint32_t excl = wexcl + (incl - ci);
        if (rr >= excl && rr < excl + ci) {                 // unique winner thread
            uint32_t need = rr - excl;
            uint32_t c = 0;
            bool done = false;
            for (int k = 0; k < 8 && !done; ++k) {
                if ((pw[k] & 0xFFFFu) == minU) {
                    if (need == 0) { c = (uint32_t)tid*16u + 2u*k;     done = true; }
                    else need--;
                }
                if (!done && (pw[k] >> 16) == minU) {
                    if (need == 0) { c = (uint32_t)tid*16u + 2u*k + 1u; done = true; }
                    else need--;
                }
            }
            g_center[b] = c;
            size_t pofs = OUT_PTS + (size_t)gq * 3;
            out[pofs + 0] = sx[c];
            out[pofs + 1] = sy[c];
            out[pofs + 2] = sz[c];
        }
        __syncthreads();                                    // bar3 (orders g_center)

        const uint32_t c = g_center[b];
        const float cx = sx[c], cy = sy[c], cz = sz[c];

        // ============ Phase B: distances + per-warp top-16 ============
        uint32_t db[16];
        uint32_t bmin = 0xFFFFFFFFu;
        int jmin = 0;
        #pragma unroll
        for (int j = 0; j < 16; ++j) {
            int i = tid + THREADS * j;
            float dx = __fsub_rn(sx[i], cx);
            float dy = __fsub_rn(sy[i], cy);
            float dz = __fsub_rn(sz[i], cz);
            float d  = __fadd_rn(__fadd_rn(__fmul_rn(dx, dx), __fmul_rn(dy, dy)),
                                 __fmul_rn(dz, dz));
            uint32_t bi = __float_as_uint(d);   // d>=0 -> bits monotone
            db[j] = bi;
            if (bi < bmin) { bmin = bi; jmin = j; }   // strict < => lowest index wins tie
        }

        uint32_t popped = 0;
        #pragma unroll 1
        for (int it = 0; it < 16; ++it) {
            uint64_t key = ((uint64_t)bmin << 32) | (uint32_t)(tid + THREADS * jmin);
            uint64_t wk = key;
            #pragma unroll
            for (int o = 16; o; o >>= 1) {
                uint64_t v = __shfl_xor_sync(0xFFFFFFFFu, wk, o);
                if (v < wk) wk = v;
            }
            if (key == wk) {                                 // unique (indices distinct)
                popped |= 1u << jmin;
                bmin = 0xFFFFFFFFu; jmin = 0;
                #pragma unroll
                for (int j = 0; j < 16; ++j) {
                    uint32_t v = db[j];
                    if (!((popped >> j) & 1u) && v < bmin) { bmin = v; jmin = j; }
                }
            }
            if (lane == 0) {
                wtD[wid * 16 + it] = (uint32_t)(wk >> 32);
                wtI[wid * 16 + it] = (uint16_t)wk;           // idx < 16384 fits
            }
        }
        __syncthreads();                                    // bar4

        // ===== warp 0: merge 32 sorted lists, write idx, bump counters =====
        if (wid == 0) {
            int pos = 0;
            uint64_t head = ((uint64_t)wtD[lane * 16] << 32) | wtI[lane * 16];
            uint32_t myIdx = 0;
            #pragma unroll 1
            for (int it = 0; it < 16; ++it) {
                uint64_t wk = head;
                #pragma unroll
                for (int o = 16; o; o >>= 1) {
                    uint64_t v = __shfl_xor_sync(0xFFFFFFFFu, wk, o);
                    if (v < wk) wk = v;
                }
                if (head == wk) {
                    pos++;
                    head = (pos < 16)
                         ? (((uint64_t)wtD[lane * 16 + pos] << 32) | wtI[lane * 16 + pos])
                         : ~0ull;
                }
                if (lane == it) myIdx = (uint32_t)(wk & 0xFFFFu);
            }
            size_t iofs = (size_t)gq * KNN;
            if (lane < 16) {
                out[iofs + lane] = (float)myIdx;
                atomicAdd(&used32[usw(myIdx >> 1)], 1u << ((myIdx & 1u) * 16));
            }
            if (lane == 16) {
                atomicAdd(&used32[usw(c >> 1)], 100u << ((c & 1u) * 16));
            }
        }
        __syncthreads();                                    // bar5 (end of step)
    }
}

extern "C" void kernel_launch(void* const* d_in, const int* in_sizes, int n_in,
                              void* d_out, int out_size) {
    (void)in_sizes; (void)n_in; (void)out_size;
    cudaFuncSetAttribute(snn_kernel,
                         cudaFuncAttributeMaxDynamicSharedMemorySize, SMEM_BYTES);
    snn_kernel<<<BATCH, THREADS, SMEM_BYTES>>>((const float*)d_in[0], (float*)d_out);
}

// round 3
// speedup vs baseline: 2.0512x; 2.0512x over previous
#include <cuda_runtime.h>
#include <cstdint>

// ============================================================================
// SampleNearestNeighborsLayer — exact JAX-semantics replay (bit-exact vs ref).
// Per batch b: 4096 sequential steps:
//   minU = min(used); cnt = #(used==minU); r = jax.random.randint(key_q,(),0,cnt)
//   center = r-th least-used point (index order); d_i = ||xyz_i - xyz_c||^2
//   ids = 16 smallest (d, i) lexicographic (== stable top_k(-d,16))
//   used[ids] += 1; used[center] += 100
// Output (float32): idx (8*4096*16) then pts (8*4096*3).
// ============================================================================

#define NQ      4096
#define NPTS    16384
#define KNN     16
#define BATCH   8
#define THREADS 1024
#define SMEM_BYTES 232448  // 128K xy(float2) + 64K z + 32K used(u16) + 3K scratch
#define FULLM   0xFFFFFFFFu

__device__ uint32_t g_hb[BATCH * NQ];
__device__ uint32_t g_lb[BATCH * NQ];
__device__ uint32_t g_center[BATCH];

__device__ __forceinline__ uint32_t rotl32(uint32_t x, int r) {
    return (x << r) | (x >> (32 - r));
}

// Threefry-2x32, 20 rounds (JAX schedule) — verified bit-exact in round 2.
__device__ __forceinline__ void tf2x32(uint32_t k0, uint32_t k1,
                                       uint32_t x0, uint32_t x1,
                                       uint32_t& o0, uint32_t& o1) {
    uint32_t ks2 = k0 ^ k1 ^ 0x1BD11BDAu;
    x0 += k0; x1 += k1;
#define TFR(r) { x0 += x1; x1 = rotl32(x1, (r)); x1 ^= x0; }
    TFR(13) TFR(15) TFR(26) TFR(6)
    x0 += k1;  x1 += ks2 + 1u;
    TFR(17) TFR(29) TFR(16) TFR(24)
    x0 += ks2; x1 += k0 + 2u;
    TFR(13) TFR(15) TFR(26) TFR(6)
    x0 += k0;  x1 += k1 + 3u;
    TFR(17) TFR(29) TFR(16) TFR(24)
    x0 += k1;  x1 += ks2 + 4u;
    TFR(13) TFR(15) TFR(26) TFR(6)
    x0 += ks2; x1 += k0 + 5u;
#undef TFR
    o0 = x0; o1 = x1;
}

// used[] stored as u16 pairs in u32 words; word W lives at usw(W).
// Makes the per-thread contiguous 8-word scan (W = 8t+k) conflict-free.
__device__ __forceinline__ uint32_t usw(uint32_t W) { return W ^ ((W >> 5) & 31u); }

// Exact squared distance, FMA-free, axis order ((dx^2+dy^2)+dz^2).
__device__ __forceinline__ uint32_t distbits(float2 p, float z,
                                             float cx, float cy, float cz) {
    float dx = __fsub_rn(p.x, cx);
    float dy = __fsub_rn(p.y, cy);
    float dz = __fsub_rn(z,   cz);
    float d  = __fadd_rn(__fadd_rn(__fmul_rn(dx, dx), __fmul_rn(dy, dy)),
                         __fmul_rn(dz, dz));
    return __float_as_uint(d);   // d >= 0 -> bit order == value order
}

extern "C" __global__ void __launch_bounds__(THREADS, 1)
snn_kernel(const float* __restrict__ xyz, float* __restrict__ out) {
    extern __shared__ unsigned char smem[];
    float2*       sxy    = (float2*)smem;                     // 128 KB
    float*        sz     = (float*)(smem + 131072);           // 64 KB
    unsigned int* used32 = (unsigned int*)(smem + 196608);    // 32 KB
    unsigned char* scr   = smem + 229376;                     // 3 KB, phase-unioned
    uint32_t* wred = (uint32_t*)scr;            // [32]  phase A (aliases wtD)
    uint32_t* wcnt = (uint32_t*)(scr + 128);    // [32]  phase A (aliases wtD)
    uint32_t* wtD  = (uint32_t*)scr;            // [512] per-warp top16 dist bits
    uint16_t* wtI  = (uint16_t*)(scr + 2048);   // [512] per-warp top16 indices

    const int tid  = threadIdx.x;
    const int b    = blockIdx.x;
    const int lane = tid & 31;
    const int wid  = tid >> 5;

    // ---- init: stage xyz (x,y as float2; z separate), zero used, RNG bits ----
    const float* g = xyz + (size_t)b * NPTS * 3;
    for (int i = tid; i < NPTS; i += THREADS) {
        sxy[i] = make_float2(g[3*i + 0], g[3*i + 1]);
        sz[i]  = g[3*i + 2];
    }
    for (int i = tid; i < NPTS/2; i += THREADS) used32[i] = 0u;

    {
        uint32_t bk0, bk1;
        tf2x32(0u, 42u, 0u, (uint32_t)b, bk0, bk1);          // batch key
        for (int q = tid; q < NQ; q += THREADS) {
            uint32_t qk0, qk1, a0, a1, e0, e1, x, y;
            tf2x32(bk0, bk1, 0u, (uint32_t)q, qk0, qk1);     // per-step key
            tf2x32(qk0, qk1, 0u, 0u, a0, a1);                // split[0]
            tf2x32(qk0, qk1, 0u, 1u, e0, e1);                // split[1]
            tf2x32(a0, a1, 0u, 0u, x, y);  g_hb[b*NQ + q] = x ^ y;
            tf2x32(e0, e1, 0u, 0u, x, y);  g_lb[b*NQ + q] = x ^ y;
        }
    }
    __syncthreads();

    const size_t OUT_PTS = (size_t)BATCH * NQ * KNN;

    for (int q = 0; q < NQ; ++q) {
        const int gq = b * NQ + q;

        // ============ Phase A: minU, cnt, rank-select center (1 bar) ========
        uint32_t lmin, ci = 0;
        {
            uint32_t pw[8];
            #pragma unroll
            for (int k = 0; k < 8; ++k)
                pw[k] = used32[usw((uint32_t)tid * 8u + (uint32_t)k)];
            uint32_t pm = pw[0];
            #pragma unroll
            for (int k = 1; k < 8; ++k) pm = __vminu2(pm, pw[k]);
            lmin = min(pm & 0xFFFFu, pm >> 16);
            lmin = __reduce_min_sync(FULLM, lmin);           // warp min
            #pragma unroll
            for (int k = 0; k < 8; ++k)
                ci += (uint32_t)((pw[k] & 0xFFFFu) == lmin)
                    + (uint32_t)((pw[k] >> 16) == lmin);
        }
        uint32_t incl = ci;                                  // scan vs own lmin
        #pragma unroll
        for (int o = 1; o < 32; o <<= 1) {
            uint32_t v = __shfl_up_sync(FULLM, incl, o);
            if (lane >= o) incl += v;
        }
        if (lane == 31) wcnt[wid] = incl;
        if (lane == 0)  wred[wid] = lmin;
        __syncthreads();                                     // bar1

        uint32_t wl  = wred[lane];
        uint32_t wcv = wcnt[lane];
        uint32_t minU = __reduce_min_sync(FULLM, wl);
        uint32_t s = (wl == minU) ? wcv : 0u;                // masked counts
        #pragma unroll
        for (int o = 1; o < 32; o <<= 1) {
            uint32_t v = __shfl_up_sync(FULLM, s, o);
            if (lane >= o) s += v;
        }
        uint32_t cnt   = __shfl_sync(FULLM, s, 31);
        uint32_t wexcl = (wid == 0) ? 0u : __shfl_sync(FULLM, s, wid - 1);

        if (lmin == minU && ci) {                            // candidate threads only
            // jax.random.randint(key_q, (), 0, cnt)
            uint32_t span = cnt;
            uint32_t mlt  = 65536u % span;
            mlt = (mlt * mlt) % span;
            uint32_t rr = ((g_hb[gq] % span) * mlt + (g_lb[gq] % span)) % span;

            uint32_t excl = wexcl + (incl - ci);
            if (rr >= excl && rr < excl + ci) {              // unique winner
                uint32_t need = rr - excl;
                uint32_t c = 0; bool done = false;
                #pragma unroll
                for (int k = 0; k < 8; ++k) {
                    uint32_t w = used32[usw((uint32_t)tid * 8u + (uint32_t)k)];
                    if (!done && (w & 0xFFFFu) == minU) {
                        if (need == 0) { c = (uint32_t)tid*16u + 2u*k; done = true; }
                        else need--;
                    }
                    if (!done && (w >> 16) == minU) {
                        if (need == 0) { c = (uint32_t)tid*16u + 2u*k + 1u; done = true; }
                        else need--;
                    }
                }
                g_center[b] = c;
                size_t pofs = OUT_PTS + (size_t)gq * 3;
                float2 cp = sxy[c];
                out[pofs + 0] = cp.x;
                out[pofs + 1] = cp.y;
                out[pofs + 2] = sz[c];
            }
        }
        __syncthreads();                                     // bar2 (center)

        const uint32_t c = g_center[b];
        const float2 cp = sxy[c];
        const float cx = cp.x, cy = cp.y, cz = sz[c];

        // ===== Phase B: distances + per-thread top-3 cache =====
        uint32_t m1 = FULLM, m2 = FULLM, m3 = FULLM;
        uint32_t j1 = 0, j2 = 0, j3 = 0;
        #pragma unroll
        for (int j = 0; j < 16; ++j) {
            int i = tid + (j << 10);
            uint32_t bi = distbits(sxy[i], sz[i], cx, cy, cz);
            if (bi < m1)      { m3=m2; j3=j2; m2=m1; j2=j1; m1=bi; j1=(uint32_t)j; }
            else if (bi < m2) { m3=m2; j3=j2; m2=bi; j2=(uint32_t)j; }
            else if (bi < m3) { m3=bi; j3=(uint32_t)j; }
        }

        // ===== per-warp pop-16 (REDUX min + index tie-break) =====
        uint32_t popped = 0;
        #pragma unroll 1
        for (int it = 0; it < 16; ++it) {
            uint32_t wmin = __reduce_min_sync(FULLM, m1);
            uint32_t cand = (m1 == wmin) ? ((uint32_t)tid | (j1 << 10)) : FULLM;
            uint32_t imin = __reduce_min_sync(FULLM, cand);
            if (cand == imin) {                              // unique winner lane
                popped |= 1u << j1;
                if (m2 != FULLM) { m1=m2; j1=j2; m2=m3; j2=j3; m3=FULLM; }
                else {                                       // rare: full rescan
                    m1 = m2 = m3 = FULLM; j1 = j2 = j3 = 0;
                    #pragma unroll
                    for (int j = 0; j < 16; ++j) {
                        int i = tid + (j << 10);
                        uint32_t v = ((popped >> j) & 1u)
                                   ? FULLM : distbits(sxy[i], sz[i], cx, cy, cz);
                        if (v < m1)      { m3=m2; j3=j2; m2=m1; j2=j1; m1=v; j1=(uint32_t)j; }
                        else if (v < m2) { m3=m2; j3=j2; m2=v; j2=(uint32_t)j; }
                        else if (v < m3) { m3=v; j3=(uint32_t)j; }
                    }
                }
            }
            if (lane == 0) {
                wtD[wid * 16 + it] = wmin;
                wtI[wid * 16 + it] = (uint16_t)imin;         // idx < 16384
            }
        }
        __syncthreads();                                     // bar3

        // ===== warp 0: merge 32 sorted lists; write idx; bump counters =====
        if (wid == 0) {
            int pos = 0;
            uint32_t hD = wtD[lane * 16];
            uint32_t hI = wtI[lane * 16];
            uint32_t myIdx = 0;
            #pragma unroll 1
            for (int it = 0; it < 16; ++it) {
                uint32_t wmin = __reduce_min_sync(FULLM, hD);
                uint32_t cand = (hD == wmin) ? hI : FULLM;
                uint32_t imin = __reduce_min_sync(FULLM, cand);
                if (cand == imin) {
                    pos++;
                    if (pos < 16) {
                        hD = wtD[lane * 16 + pos];
                        hI = wtI[lane * 16 + pos];
                    } else { hD = FULLM; hI = FULLM; }
                }
                if (lane == it) myIdx = imin;
            }
            size_t iofs = (size_t)gq * KNN;
            if (lane < 16) {
                out[iofs + lane] = (float)myIdx;
                atomicAdd(&used32[usw(myIdx >> 1)], 1u << ((myIdx & 1u) * 16));
            }
            if (lane == 16) {
                atomicAdd(&used32[usw(c >> 1)], 100u << ((c & 1u) * 16));
            }
        }
        __syncthreads();                                     // bar4 (end of step)
    }
}

extern "C" void kernel_launch(void* const* d_in, const int* in_sizes, int n_in,
                              void* d_out, int out_size) {
    (void)in_sizes; (void)n_in; (void)out_size;
    cudaFuncSetAttribute(snn_kernel,
                         cudaFuncAttributeMaxDynamicSharedMemorySize, SMEM_BYTES);
    snn_kernel<<<BATCH, THREADS, SMEM_BYTES>>>((const float*)d_in[0], (float*)d_out);
}

// round 5
// speedup vs baseline: 3.1980x; 1.5591x over previous
#include <cuda_runtime.h>
#include <cstdint>

// ============================================================================
// SampleNearestNeighborsLayer — exact JAX-semantics replay (bit-exact).
// Per batch b: 4096 sequential steps:
//   minU=min(used); cnt=#(used==minU); r=jax.random.randint(key_q,(),0,cnt)
//   center = r-th least-used point (index order); d_i = ||xyz_i - xyz_c||^2
//   ids = 16 smallest (d,i) lexicographic; used[ids]+=1; used[center]+=100
// Output (float32): idx (8*4096*16) then pts (8*4096*3).
//
// Selection: T = max over 16 warp-min distances certifies >=16 elements <= T,
// so the global top-16 all satisfy d <= T. Compact all d<=T (E[C]~54,
// coupon-collector) into 128 u64 keys; warp 0 pops 16 by REDUX. If C > 128
// (P ~ 4e-3/step), take the exact per-warp pop-16 + merge fallback instead.
// Both paths exact; choice is deterministic.
// ============================================================================

#define NQ      4096
#define NPTS    16384
#define KNN     16
#define BATCH   8
#define THREADS 512
#define NWARP   16
#define PPT     32
#define CAP     128
#define SMEM_BYTES 232448
#define FULLM   0xFFFFFFFFu

__device__ uint64_t g_hb64[BATCH * NQ];   // packed (higher_bits<<32)|lower_bits

__device__ __forceinline__ uint32_t rotl32(uint32_t x, int r) {
    return (x << r) | (x >> (32 - r));
}

// Threefry-2x32, 20 rounds (JAX schedule) — verified bit-exact on HW.
__device__ __forceinline__ void tf2x32(uint32_t k0, uint32_t k1,
                                       uint32_t x0, uint32_t x1,
                                       uint32_t& o0, uint32_t& o1) {
    uint32_t ks2 = k0 ^ k1 ^ 0x1BD11BDAu;
    x0 += k0; x1 += k1;
#define TFR(r) { x0 += x1; x1 = rotl32(x1, (r)); x1 ^= x0; }
    TFR(13) TFR(15) TFR(26) TFR(6)
    x0 += k1;  x1 += ks2 + 1u;
    TFR(17) TFR(29) TFR(16) TFR(24)
    x0 += ks2; x1 += k0 + 2u;
    TFR(13) TFR(15) TFR(26) TFR(6)
    x0 += k0;  x1 += k1 + 3u;
    TFR(17) TFR(29) TFR(16) TFR(24)
    x0 += k1;  x1 += ks2 + 4u;
    TFR(13) TFR(15) TFR(26) TFR(6)
    x0 += ks2; x1 += k0 + 5u;
#undef TFR
    o0 = x0; o1 = x1;
}

// used[] as u16 pairs in u32 words; word W stored at usw(W).
// For W = 16t+k (t=lane): bank = (16(t&1)+k) ^ ((t>>1)&31) -> conflict-free.
__device__ __forceinline__ uint32_t usw(uint32_t W) { return W ^ ((W >> 5) & 31u); }

// Exact squared distance, FMA-free, axis order ((dx^2+dy^2)+dz^2).
__device__ __forceinline__ uint32_t distbits(float2 p, float z,
                                             float cx, float cy, float cz) {
    float dx = __fsub_rn(p.x, cx);
    float dy = __fsub_rn(p.y, cy);
    float dz = __fsub_rn(z,   cz);
    float d  = __fadd_rn(__fadd_rn(__fmul_rn(dx, dx), __fmul_rn(dy, dy)),
                         __fmul_rn(dz, dz));
    return __float_as_uint(d);   // d >= 0 -> bit order == value order
}

extern "C" __global__ void __launch_bounds__(THREADS, 1)
snn_kernel(const float* __restrict__ xyz, float* __restrict__ out) {
    extern __shared__ unsigned char smem[];
    float2*       sxy    = (float2*)smem;                     // 128 KB
    float*        sz     = (float*)(smem + 131072);           // 64 KB
    unsigned int* used32 = (unsigned int*)(smem + 196608);    // 32 KB
    unsigned char* scr   = smem + 229376;                     // 3 KB
    uint64_t* buf   = (uint64_t*)scr;             // [128]   compaction keys
    uint32_t* wtD   = (uint32_t*)(scr + 1024);    // [16*16] fallback dist lists
    uint16_t* wtI   = (uint16_t*)(scr + 2048);    // [16*16] fallback idx lists
    uint32_t* wred  = (uint32_t*)(scr + 2560);    // [16] per-warp min used
    uint32_t* wcnt  = (uint32_t*)(scr + 2624);    // [16] per-warp cand scan
    uint32_t* wmind = (uint32_t*)(scr + 2688);    // [16] per-warp min dist
    uint32_t* scnt  = (uint32_t*)(scr + 2752);    // compaction counter
    uint32_t* scen  = (uint32_t*)(scr + 2756);    // center index

    const int tid  = threadIdx.x;
    const int b    = blockIdx.x;
    const int lane = tid & 31;
    const int wid  = tid >> 5;

    // ---- init: stage xyz (x,y float2; z separate), zero used, RNG bits ----
    const float* g = xyz + (size_t)b * NPTS * 3;
    for (int i = tid; i < NPTS; i += THREADS) {
        sxy[i] = make_float2(g[3*i + 0], g[3*i + 1]);
        sz[i]  = g[3*i + 2];
    }
    for (int i = tid; i < NPTS/2; i += THREADS) used32[i] = 0u;

    {
        uint32_t bk0, bk1;
        tf2x32(0u, 42u, 0u, (uint32_t)b, bk0, bk1);          // batch key
        for (int q = tid; q < NQ; q += THREADS) {
            uint32_t qk0, qk1, a0, a1, e0, e1, x, y, hb, lb;
            tf2x32(bk0, bk1, 0u, (uint32_t)q, qk0, qk1);     // per-step key
            tf2x32(qk0, qk1, 0u, 0u, a0, a1);                // split[0]
            tf2x32(qk0, qk1, 0u, 1u, e0, e1);                // split[1]
            tf2x32(a0, a1, 0u, 0u, x, y);  hb = x ^ y;
            tf2x32(e0, e1, 0u, 0u, x, y);  lb = x ^ y;
            g_hb64[b*NQ + q] = ((uint64_t)hb << 32) | lb;
        }
    }
    __syncthreads();

    const size_t OUT_PTS = (size_t)BATCH * NQ * KNN;

    for (int q = 0; q < NQ; ++q) {
        const int gq = b * NQ + q;
        const uint64_t hb64 = g_hb64[gq];                    // early LDG

        // ===== Phase A: minU, cnt, rank-select center =====
        uint32_t pw[16];
        #pragma unroll
        for (int k = 0; k < 16; ++k)
            pw[k] = used32[usw((uint32_t)tid * 16u + (uint32_t)k)];
        uint32_t pm = pw[0];
        #pragma unroll
        for (int k = 1; k < 16; ++k) pm = __vminu2(pm, pw[k]);
        uint32_t lmin = min(pm & 0xFFFFu, pm >> 16);
        lmin = __reduce_min_sync(FULLM, lmin);               // warp min
        uint32_t ci = 0;
        #pragma unroll
        for (int k = 0; k < 16; ++k)
            ci += (uint32_t)((pw[k] & 0xFFFFu) == lmin)
                + (uint32_t)((pw[k] >> 16) == lmin);
        uint32_t incl = ci;                                  // warp scan
        #pragma unroll
        for (int o = 1; o < 32; o <<= 1) {
            uint32_t v = __shfl_up_sync(FULLM, incl, o);
            if (lane >= o) incl += v;
        }
        if (lane == 31) wcnt[wid] = incl;
        if (lane == 0)  wred[wid] = lmin;
        __syncthreads();                                     // bar1

        uint32_t wl  = wred[lane & 15];
        uint32_t wcv = wcnt[lane & 15];
        uint32_t minU = __reduce_min_sync(FULLM, wl);        // dups harmless
        uint32_t s = (lane < NWARP && wl == minU) ? wcv : 0u;
        #pragma unroll
        for (int o = 1; o < 32; o <<= 1) {
            uint32_t v = __shfl_up_sync(FULLM, s, o);
            if (lane >= o) s += v;
        }
        uint32_t cntA  = __shfl_sync(FULLM, s, 15);
        uint32_t wexcl = (wid == 0) ? 0u : __shfl_sync(FULLM, s, wid - 1);

        if (lmin == minU && ci) {
            // randint: ((hb%s)*((65536%s)^2%s)+lb%s)%s == (hb*2^32+lb)%s
            uint32_t rr = (uint32_t)(hb64 % (uint64_t)cntA);
            uint32_t excl = wexcl + (incl - ci);
            if (rr >= excl && rr < excl + ci) {              // unique winner
                uint32_t need = rr - excl;
                uint32_t c = 0; bool done = false;
                #pragma unroll
                for (int k = 0; k < 16; ++k) {
                    if (!done && (pw[k] & 0xFFFFu) == minU) {
                        if (need == 0) { c = (uint32_t)tid*32u + 2u*k; done = true; }
                        else need--;
                    }
                    if (!done && (pw[k] >> 16) == minU) {
                        if (need == 0) { c = (uint32_t)tid*32u + 2u*k + 1u; done = true; }
                        else need--;
                    }
                }
                *scen = c;
                size_t pofs = OUT_PTS + (size_t)gq * 3;
                float2 cp = sxy[c];
                out[pofs + 0] = cp.x;
                out[pofs + 1] = cp.y;
                out[pofs + 2] = sz[c];
            }
        }
        __syncthreads();                                     // bar2

        const uint32_t c = *scen;
        const float2 cp = sxy[c];
        const float cx = cp.x, cy = cp.y, cz = sz[c];
        // reset compaction state (prev consumer finished before bar5/bar1/bar2)
        if (tid < CAP) buf[tid] = ~0ull;
        if (tid == CAP) *scnt = 0u;

        // ===== Phase B: distances (live in regs), per-warp min =====
        uint32_t db[PPT];
        #pragma unroll
        for (int j = 0; j < PPT; ++j) {
            int i = tid + (j << 9);
            db[j] = distbits(sxy[i], sz[i], cx, cy, cz);
        }
        uint32_t tm = db[0];
        #pragma unroll
        for (int j = 1; j < PPT; ++j) tm = min(tm, db[j]);
        tm = __reduce_min_sync(FULLM, tm);
        if (lane == 0) wmind[wid] = tm;
        __syncthreads();                                     // bar3

        // T certifies >= 16 elements <= T  =>  top-16 subset of {d <= T}
        uint32_t T = __reduce_max_sync(FULLM, wmind[lane & 15]);
        uint32_t nc = 0;
        #pragma unroll
        for (int j = 0; j < PPT; ++j) nc += (uint32_t)(db[j] <= T);
        if (nc) {
            uint32_t slot = atomicAdd(scnt, nc);
            #pragma unroll
            for (int j = 0; j < PPT; ++j) {
                if (db[j] <= T) {
                    if (slot < CAP)
                        buf[slot] = ((uint64_t)db[j] << 32)
                                  | (uint32_t)(tid + (j << 9));
                    slot++;
                }
            }
        }
        __syncthreads();                                     // bar4

        const uint32_t C = *scnt;                            // block-uniform
        if (C <= CAP) {
            // ===== fast path: warp 0 pops 16 smallest of <=128 keys =====
            if (wid == 0) {
                uint64_t v0 = buf[lane];
                uint64_t v1 = buf[lane + 32];
                uint64_t v2 = buf[lane + 64];
                uint64_t v3 = buf[lane + 96];
                uint32_t myIdx = 0;
                #pragma unroll 1
                for (int it = 0; it < KNN; ++it) {
                    uint64_t a = (v0 < v1) ? v0 : v1;  int ra = (v0 < v1) ? 0 : 1;
                    uint64_t e = (v2 < v3) ? v2 : v3;  int re = (v2 < v3) ? 2 : 3;
                    uint64_t lm = (a < e) ? a : e;     int rm = (a < e) ? ra : re;
                    uint32_t hi = (uint32_t)(lm >> 32);
                    uint32_t wmin = __reduce_min_sync(FULLM, hi);
                    uint32_t cand = (hi == wmin) ? (uint32_t)lm : FULLM;
                    uint32_t imin = __reduce_min_sync(FULLM, cand);
                    if (cand == imin) {                      // unique winner lane
                        if      (rm == 0) v0 = ~0ull;
                        else if (rm == 1) v1 = ~0ull;
                        else if (rm == 2) v2 = ~0ull;
                        else              v3 = ~0ull;
                    }
                    if (lane == it) myIdx = imin;
                }
                if (lane < KNN) {
                    out[(size_t)gq * KNN + lane] = (float)myIdx;
                    atomicAdd(&used32[usw(myIdx >> 1)], 1u << ((myIdx & 1u) * 16));
                }
                if (lane == KNN)
                    atomicAdd(&used32[usw(c >> 1)], 100u << ((c & 1u) * 16));
            }
        } else {
            // ===== exact fallback (~0.4% of steps): per-warp pop-16 =====
            uint32_t m1 = FULLM, m2 = FULLM, m3 = FULLM;
            uint32_t j1 = 0, j2 = 0, j3 = 0;
            #pragma unroll
            for (int j = 0; j < PPT; ++j) {
                uint32_t v = db[j];
                if (v < m1)      { m3=m2; j3=j2; m2=m1; j2=j1; m1=v; j1=(uint32_t)j; }
                else if (v < m2) { m3=m2; j3=j2; m2=v; j2=(uint32_t)j; }
                else if (v < m3) { m3=v; j3=(uint32_t)j; }
            }
            uint32_t popped = 0;
            #pragma unroll 1
            for (int it = 0; it < KNN; ++it) {
                uint32_t wmin = __reduce_min_sync(FULLM, m1);
                uint32_t cand = (m1 == wmin) ? ((uint32_t)tid + (j1 << 9)) : FULLM;
                uint32_t imin = __reduce_min_sync(FULLM, cand);
                if (cand == imin) {
                    popped |= 1u << j1;
                    if (m2 != FULLM) { m1=m2; j1=j2; m2=m3; j2=j3; m3=FULLM; }
                    else {                                   // rare full rescan
                        m1 = m2 = m3 = FULLM; j1 = j2 = j3 = 0;
                        #pragma unroll
                        for (int j = 0; j < PPT; ++j) {
                            uint32_t v = ((popped >> j) & 1u) ? FULLM : db[j];
                            if (v < m1)      { m3=m2; j3=j2; m2=m1; j2=j1; m1=v; j1=(uint32_t)j; }
                            else if (v < m2) { m3=m2; j3=j2; m2=v; j2=(uint32_t)j; }
                            else if (v < m3) { m3=v; j3=(uint32_t)j; }
                        }
                    }
                }
                if (lane == 0) {
                    wtD[wid * 16 + it] = wmin;
                    wtI[wid * 16 + it] = (uint16_t)imin;
                }
            }
            __syncthreads();                                 // fb-bar (uniform)
            if (wid == 0) {
                int pos = 0;
                uint32_t hD = (lane < NWARP) ? wtD[lane * 16] : FULLM;
                uint32_t hI = (lane < NWARP) ? (uint32_t)wtI[lane * 16] : FULLM;
                uint32_t myIdx = 0;
                #pragma unroll 1
                for (int it = 0; it < KNN; ++it) {
                    uint32_t wmin = __reduce_min_sync(FULLM, hD);
                    uint32_t cand = (hD == wmin) ? hI : FULLM;
                    uint32_t imin = __reduce_min_sync(FULLM, cand);
                    if (cand == imin) {
                        pos++;
                        if (pos < 16) {
                            hD = wtD[lane * 16 + pos];
                            hI = wtI[lane * 16 + pos];
                        } else { hD = FULLM; hI = FULLM; }
                    }
                    if (lane == it) myIdx = imin;
                }
                if (lane < KNN) {
                    out[(size_t)gq * KNN + lane] = (float)myIdx;
                    atomicAdd(&used32[usw(myIdx >> 1)], 1u << ((myIdx & 1u) * 16));
                }
                if (lane == KNN)
                    atomicAdd(&used32[usw(c >> 1)], 100u << ((c & 1u) * 16));
            }
        }
        __syncthreads();                                     // bar5
    }
}

extern "C" void kernel_launch(void* const* d_in, const int* in_sizes, int n_in,
                              void* d_out, int out_size) {
    (void)in_sizes; (void)n_in; (void)out_size;
    cudaFuncSetAttribute(snn_kernel,
                         cudaFuncAttributeMaxDynamicSharedMemorySize, SMEM_BYTES);
    snn_kernel<<<BATCH, THREADS, SMEM_BYTES>>>((const float*)d_in[0], (float*)d_out);
}

// round 6
// speedup vs baseline: 4.3137x; 1.3489x over previous
#include <cuda_runtime.h>
#include <cstdint>

// ============================================================================
// SampleNearestNeighborsLayer — exact JAX-semantics replay (bit-exact).
// Per batch b: 4096 sequential steps:
//   minU=min(used); cnt=#(used==minU); r=jax.random.randint(key_q,(),0,cnt)
//   center = r-th least-used point (index order); d_i = ||xyz_i - xyz_c||^2
//   ids = 16 smallest (d,i) lexicographic; used[ids]+=1; used[center]+=100
// Output (float32): idx (8*4096*16) then pts (8*4096*3).
//
// Selection: T = max over 16 warp-min distances certifies >=16 elements <= T.
// Compact all d<=T (E[C]~54) into u64 (dist<<32|idx) keys; winners = keys of
// rank < 16, rank computed in parallel (rank r == r-th smallest, unique keys).
// If C > 128 (P~4e-3/step) use the exact per-warp pop-16 + merge fallback.
// ============================================================================

#define NQ      4096
#define NPTS    16384
#define KNN     16
#define BATCH   8
#define THREADS 512
#define NWARP   16
#define PPT     32
#define CAP     128
#define SMEM_BYTES 232448
#define FULLM   0xFFFFFFFFu

__device__ uint64_t g_hb64[BATCH * NQ];   // packed (higher_bits<<32)|lower_bits

__device__ __forceinline__ uint32_t rotl32(uint32_t x, int r) {
    return (x << r) | (x >> (32 - r));
}

// Threefry-2x32, 20 rounds (JAX schedule) — verified bit-exact on HW.
__device__ __forceinline__ void tf2x32(uint32_t k0, uint32_t k1,
                                       uint32_t x0, uint32_t x1,
                                       uint32_t& o0, uint32_t& o1) {
    uint32_t ks2 = k0 ^ k1 ^ 0x1BD11BDAu;
    x0 += k0; x1 += k1;
#define TFR(r) { x0 += x1; x1 = rotl32(x1, (r)); x1 ^= x0; }
    TFR(13) TFR(15) TFR(26) TFR(6)
    x0 += k1;  x1 += ks2 + 1u;
    TFR(17) TFR(29) TFR(16) TFR(24)
    x0 += ks2; x1 += k0 + 2u;
    TFR(13) TFR(15) TFR(26) TFR(6)
    x0 += k0;  x1 += k1 + 3u;
    TFR(17) TFR(29) TFR(16) TFR(24)
    x0 += k1;  x1 += ks2 + 4u;
    TFR(13) TFR(15) TFR(26) TFR(6)
    x0 += ks2; x1 += k0 + 5u;
#undef TFR
    o0 = x0; o1 = x1;
}

// used[] as u16 pairs in u32 words; word W stored at usw(W) (conflict-free
// for the per-thread 16-word scan, verified by bank walk).
__device__ __forceinline__ uint32_t usw(uint32_t W) { return W ^ ((W >> 5) & 31u); }

// Exact squared distance, FMA-free, axis order ((dx^2+dy^2)+dz^2).
__device__ __forceinline__ uint32_t distbits(float2 p, float z,
                                             float cx, float cy, float cz) {
    float dx = __fsub_rn(p.x, cx);
    float dy = __fsub_rn(p.y, cy);
    float dz = __fsub_rn(z,   cz);
    float d  = __fadd_rn(__fadd_rn(__fmul_rn(dx, dx), __fmul_rn(dy, dy)),
                         __fmul_rn(dz, dz));
    return __float_as_uint(d);   // d >= 0 -> bit order == value order
}

extern "C" __global__ void __launch_bounds__(THREADS, 1)
snn_kernel(const float* __restrict__ xyz, float* __restrict__ out) {
    extern __shared__ unsigned char smem[];
    float2*       sxy    = (float2*)smem;                     // 128 KB
    float*        sz     = (float*)(smem + 131072);           // 64 KB
    unsigned int* used32 = (unsigned int*)(smem + 196608);    // 32 KB
    unsigned char* scr   = smem + 229376;                     // 3 KB
    uint64_t* buf   = (uint64_t*)scr;             // [128]   compaction keys
    uint32_t* wtD   = (uint32_t*)(scr + 1024);    // [16*16] fallback dist lists
    uint16_t* wtI   = (uint16_t*)(scr + 2048);    // [16*16] fallback idx lists
    uint32_t* wred  = (uint32_t*)(scr + 2560);    // [16] per-warp min used
    uint32_t* wcnt  = (uint32_t*)(scr + 2624);    // [16] per-warp cand scan
    uint32_t* wmind = (uint32_t*)(scr + 2688);    // [16] per-warp min dist
    uint32_t* scnt  = (uint32_t*)(scr + 2752);    // compaction counter
    uint32_t* scen  = (uint32_t*)(scr + 2756);    // center index

    const int tid  = threadIdx.x;
    const int b    = blockIdx.x;
    const int lane = tid & 31;
    const int wid  = tid >> 5;

    // ---- init: stage xyz (x,y float2; z separate), zero used, RNG bits ----
    const float* g = xyz + (size_t)b * NPTS * 3;
    for (int i = tid; i < NPTS; i += THREADS) {
        sxy[i] = make_float2(g[3*i + 0], g[3*i + 1]);
        sz[i]  = g[3*i + 2];
    }
    for (int i = tid; i < NPTS/2; i += THREADS) used32[i] = 0u;

    {
        uint32_t bk0, bk1;
        tf2x32(0u, 42u, 0u, (uint32_t)b, bk0, bk1);          // batch key
        for (int q = tid; q < NQ; q += THREADS) {
            uint32_t qk0, qk1, a0, a1, e0, e1, x, y, hb, lb;
            tf2x32(bk0, bk1, 0u, (uint32_t)q, qk0, qk1);     // per-step key
            tf2x32(qk0, qk1, 0u, 0u, a0, a1);                // split[0]
            tf2x32(qk0, qk1, 0u, 1u, e0, e1);                // split[1]
            tf2x32(a0, a1, 0u, 0u, x, y);  hb = x ^ y;
            tf2x32(e0, e1, 0u, 0u, x, y);  lb = x ^ y;
            g_hb64[b*NQ + q] = ((uint64_t)hb << 32) | lb;
        }
    }
    __syncthreads();

    const size_t OUT_PTS = (size_t)BATCH * NQ * KNN;

    for (int q = 0; q < NQ; ++q) {
        const int gq = b * NQ + q;
        const uint64_t hb64 = g_hb64[gq];                    // early LDG

        // ===== Phase A: minU, cnt, rank-select center =====
        uint32_t pw[16];
        #pragma unroll
        for (int k = 0; k < 16; ++k)
            pw[k] = used32[usw((uint32_t)tid * 16u + (uint32_t)k)];
        uint32_t pm = pw[0];
        #pragma unroll
        for (int k = 1; k < 16; ++k) pm = __vminu2(pm, pw[k]);
        uint32_t lmin = min(pm & 0xFFFFu, pm >> 16);
        lmin = __reduce_min_sync(FULLM, lmin);               // warp min
        uint32_t ci = 0;
        #pragma unroll
        for (int k = 0; k < 16; ++k)
            ci += (uint32_t)((pw[k] & 0xFFFFu) == lmin)
                + (uint32_t)((pw[k] >> 16) == lmin);
        uint32_t incl = ci;                                  // warp scan
        #pragma unroll
        for (int o = 1; o < 32; o <<= 1) {
            uint32_t v = __shfl_up_sync(FULLM, incl, o);
            if (lane >= o) incl += v;
        }
        if (lane == 31) wcnt[wid] = incl;
        if (lane == 0)  wred[wid] = lmin;
        __syncthreads();                                     // bar1

        uint32_t wl  = wred[lane & 15];
        uint32_t wcv = wcnt[lane & 15];
        uint32_t minU = __reduce_min_sync(FULLM, wl);        // dups harmless
        uint32_t s = (lane < NWARP && wl == minU) ? wcv : 0u;
        #pragma unroll
        for (int o = 1; o < 32; o <<= 1) {
            uint32_t v = __shfl_up_sync(FULLM, s, o);
            if (lane >= o) s += v;
        }
        uint32_t cntA  = __shfl_sync(FULLM, s, 15);
        uint32_t wexcl = (wid == 0) ? 0u : __shfl_sync(FULLM, s, wid - 1);

        if (lmin == minU && ci) {
            // randint (all u32, verified): ((hb%s)*((65536%s)^2%s)+lb%s)%s
            uint32_t sp = cntA;
            uint32_t hbv = (uint32_t)(hb64 >> 32);
            uint32_t lbv = (uint32_t)hb64;
            uint32_t mlt = 65536u % sp;
            mlt = (mlt * mlt) % sp;                          // < sp <= 16384
            uint32_t rr = ((hbv % sp) * mlt + (lbv % sp)) % sp;
            uint32_t excl = wexcl + (incl - ci);
            if (rr >= excl && rr < excl + ci) {              // unique winner
                uint32_t need = rr - excl;
                uint32_t c = 0; bool done = false;
                #pragma unroll
                for (int k = 0; k < 16; ++k) {
                    if (!done && (pw[k] & 0xFFFFu) == minU) {
                        if (need == 0) { c = (uint32_t)tid*32u + 2u*k; done = true; }
                        else need--;
                    }
                    if (!done && (pw[k] >> 16) == minU) {
                        if (need == 0) { c = (uint32_t)tid*32u + 2u*k + 1u; done = true; }
                        else need--;
                    }
                }
                *scen = c;
                size_t pofs = OUT_PTS + (size_t)gq * 3;
                float2 cp = sxy[c];
                out[pofs + 0] = cp.x;
                out[pofs + 1] = cp.y;
                out[pofs + 2] = sz[c];
            }
        }
        __syncthreads();                                     // bar2

        const uint32_t c = *scen;
        const float2 cp = sxy[c];
        const float cx = cp.x, cy = cp.y, cz = sz[c];
        if (tid == 0) *scnt = 0u;

        // ===== Phase B: distances (live in regs), per-warp min =====
        uint32_t db[PPT];
        #pragma unroll
        for (int j = 0; j < PPT; ++j) {
            int i = tid + (j << 9);
            db[j] = distbits(sxy[i], sz[i], cx, cy, cz);
        }
        uint32_t tm = db[0];
        #pragma unroll
        for (int j = 1; j < PPT; ++j) tm = min(tm, db[j]);
        tm = __reduce_min_sync(FULLM, tm);
        if (lane == 0) wmind[wid] = tm;
        __syncthreads();                                     // bar3

        // T certifies >= 16 elements <= T  =>  top-16 subset of {d <= T}
        uint32_t T = __reduce_max_sync(FULLM, wmind[lane & 15]);
        uint32_t nc = 0;
        #pragma unroll
        for (int j = 0; j < PPT; ++j) nc += (uint32_t)(db[j] <= T);
        if (nc) {
            uint32_t slot = atomicAdd(scnt, nc);
            #pragma unroll
            for (int j = 0; j < PPT; ++j) {
                if (db[j] <= T) {
                    if (slot < CAP)
                        buf[slot] = ((uint64_t)db[j] << 32)
                                  | (uint32_t)(tid + (j << 9));
                    slot++;
                }
            }
        }
        __syncthreads();                                     // bar4

        const uint32_t C = *scnt;                            // block-uniform
        if (C <= CAP) {
            // ===== fast path: parallel rank of C unique u64 keys =====
            // rank r key == r-th smallest; ranks 0..15 are the exact,
            // already-ordered top_k winners (lex (d, idx), C >= 16 certified).
            if ((uint32_t)tid < C) {
                uint64_t my = buf[tid];
                uint32_t rank = 0;
                int j = 0;
                for (; j + 4 <= (int)C; j += 4) {
                    rank += (uint32_t)(buf[j]     < my);
                    rank += (uint32_t)(buf[j + 1] < my);
                    rank += (uint32_t)(buf[j + 2] < my);
                    rank += (uint32_t)(buf[j + 3] < my);
                }
                for (; j < (int)C; ++j) rank += (uint32_t)(buf[j] < my);
                if (rank < KNN) {
                    uint32_t myIdx = (uint32_t)my;
                    out[(size_t)gq * KNN + rank] = (float)myIdx;
                    atomicAdd(&used32[usw(myIdx >> 1)], 1u << ((myIdx & 1u) * 16));
                }
            }
            if (tid == THREADS - 1)
                atomicAdd(&used32[usw(c >> 1)], 100u << ((c & 1u) * 16));
        } else {
            // ===== exact fallback (~0.4% of steps): per-warp pop-16 =====
            uint32_t m1 = FULLM, m2 = FULLM, m3 = FULLM;
            uint32_t j1 = 0, j2 = 0, j3 = 0;
            #pragma unroll
            for (int j = 0; j < PPT; ++j) {
                uint32_t v = db[j];
                if (v < m1)      { m3=m2; j3=j2; m2=m1; j2=j1; m1=v; j1=(uint32_t)j; }
                else if (v < m2) { m3=m2; j3=j2; m2=v; j2=(uint32_t)j; }
                else if (v < m3) { m3=v; j3=(uint32_t)j; }
            }
            uint32_t popped = 0;
            #pragma unroll 1
            for (int it = 0; it < KNN; ++it) {
                uint32_t wmin = __reduce_min_sync(FULLM, m1);
                uint32_t cand = (m1 == wmin) ? ((uint32_t)tid + (j1 << 9)) : FULLM;
                uint32_t imin = __reduce_min_sync(FULLM, cand);
                if (cand == imin) {
                    popped |= 1u << j1;
                    if (m2 != FULLM) { m1=m2; j1=j2; m2=m3; j2=j3; m3=FULLM; }
                    else {                                   // rare full rescan
                        m1 = m2 = m3 = FULLM; j1 = j2 = j3 = 0;
                        #pragma unroll
                        for (int j = 0; j < PPT; ++j) {
                            uint32_t v = ((popped >> j) & 1u) ? FULLM : db[j];
                            if (v < m1)      { m3=m2; j3=j2; m2=m1; j2=j1; m1=v; j1=(uint32_t)j; }
                            else if (v < m2) { m3=m2; j3=j2; m2=v; j2=(uint32_t)j; }
                            else if (v < m3) { m3=v; j3=(uint32_t)j; }
                        }
                    }
                }
                if (lane == 0) {
                    wtD[wid * 16 + it] = wmin;
                    wtI[wid * 16 + it] = (uint16_t)imin;
                }
            }
            __syncthreads();                                 // fb-bar (uniform)
            if (wid == 0) {
                int pos = 0;
                uint32_t hD = (lane < NWARP) ? wtD[lane * 16] : FULLM;
                uint32_t hI = (lane < NWARP) ? (uint32_t)wtI[lane * 16] : FULLM;
                uint32_t myIdx = 0;
                #pragma unroll 1
                for (int it = 0; it < KNN; ++it) {
                    uint32_t wmin = __reduce_min_sync(FULLM, hD);
                    uint32_t cand = (hD == wmin) ? hI : FULLM;
                    uint32_t imin = __reduce_min_sync(FULLM, cand);
                    if (cand == imin) {
                        pos++;
                        if (pos < 16) {
                            hD = wtD[lane * 16 + pos];
                            hI = wtI[lane * 16 + pos];
                        } else { hD = FULLM; hI = FULLM; }
                    }
                    if (lane == it) myIdx = imin;
                }
                if (lane < KNN) {
                    out[(size_t)gq * KNN + lane] = (float)myIdx;
                    atomicAdd(&used32[usw(myIdx >> 1)], 1u << ((myIdx & 1u) * 16));
                }
                if (lane == KNN)
                    atomicAdd(&used32[usw(c >> 1)], 100u << ((c & 1u) * 16));
            }
        }
        __syncthreads();                                     // bar5
    }
}

extern "C" void kernel_launch(void* const* d_in, const int* in_sizes, int n_in,
                              void* d_out, int out_size) {
    (void)in_sizes; (void)n_in; (void)out_size;
    cudaFuncSetAttribute(snn_kernel,
                         cudaFuncAttributeMaxDynamicSharedMemorySize, SMEM_BYTES);
    snn_kernel<<<BATCH, THREADS, SMEM_BYTES>>>((const float*)d_in[0], (float*)d_out);
}